// round 10
// baseline (speedup 1.0000x reference)
#include <cuda_runtime.h>
#include <math.h>

// WindAdaptivePooling: out[b,c] = mean(x[b,c,:,:]) * softmax(wind_weights)[wind_indices[b]]
// x: [64, 1280, 32, 32] fp32 = 335.5 MB single-pass stream -> HBM-bound.
// FINAL (R10 = R8 config). History:
//   R1/R5 52.7us baseline (one-shot grid, 8x float4 MLP=8/warp, DRAM 84.9%).
//   R2 __ldcs: neutral (B300 LTS cap is path-independent).
//   R3 persistent: regs 44 -> occ 5/SM -> DRAM 80.3%. REGRESSED.
//   R4 persistent + launch_bounds reg cap: MLP serialized -> 77.5%. REGRESSED.
//   R6 softmax in load shadow: 52.2us but regs 57 (occ 39; DRAM invariant to occ).
//   R7 lane-parallel softmax AFTER reduce: 51.9us, regs 32, DRAM 85.3%. WIN.
//   R8 512-thr blocks (5120 CTAs): 51.7us, DRAM 85.4% (6.76 TB/s). WIN (small).
//   R9 1024-thr blocks: neutral (51.74us).
// Conclusion: 85.4% DRAM = sm_103a pure-read roofline for this pattern; all
// identified mechanisms tested. This kernel is final.

__global__ void __launch_bounds__(512) wind_pool_kernel(
    const float* __restrict__ x,
    const int*   __restrict__ wind_indices,
    const float* __restrict__ wind_weights,
    float*       __restrict__ out,
    int n_rows,   // B*C
    int C,
    int hw,       // H*W elements per row
    int n_winds)
{
    int warp = (blockIdx.x * (int)blockDim.x + (int)threadIdx.x) >> 5;
    int lane = threadIdx.x & 31;
    if (warp >= n_rows) return;

    const float4* row4 = reinterpret_cast<const float4*>(x + (size_t)warp * hw);
    int n4 = hw >> 2;

    float s = 0.0f;
    if (n4 == 256) {
        // Fast path: HW=1024. 8 fully-unrolled independent float4 loads (MLP=8).
        float4 v0 = row4[lane + 0 * 32];
        float4 v1 = row4[lane + 1 * 32];
        float4 v2 = row4[lane + 2 * 32];
        float4 v3 = row4[lane + 3 * 32];
        float4 v4 = row4[lane + 4 * 32];
        float4 v5 = row4[lane + 5 * 32];
        float4 v6 = row4[lane + 6 * 32];
        float4 v7 = row4[lane + 7 * 32];
        s = (v0.x + v0.y + v0.z + v0.w) + (v1.x + v1.y + v1.z + v1.w)
          + (v2.x + v2.y + v2.z + v2.w) + (v3.x + v3.y + v3.z + v3.w)
          + (v4.x + v4.y + v4.z + v4.w) + (v5.x + v5.y + v5.z + v5.w)
          + (v6.x + v6.y + v6.z + v6.w) + (v7.x + v7.y + v7.z + v7.w);
    } else {
        for (int i = lane; i < n4; i += 32) {
            float4 v = row4[i];
            s += v.x + v.y + v.z + v.w;
        }
    }

    // Warp butterfly reduce of the row sum.
    #pragma unroll
    for (int o = 16; o > 0; o >>= 1)
        s += __shfl_xor_sync(0xFFFFFFFFu, s, o);

    // Lane-parallel softmax gather (temps live only AFTER loads retire -> 32 regs).
    int b  = warp / C;
    int wi = wind_indices[b];   // broadcast, L1/L2-hot
    float scale;
    if (n_winds <= 32) {
        float wv = (lane < n_winds) ? wind_weights[lane] : -INFINITY;
        float mx = wv;
        #pragma unroll
        for (int o = 16; o > 0; o >>= 1)
            mx = fmaxf(mx, __shfl_xor_sync(0xFFFFFFFFu, mx, o));
        float e = (lane < n_winds) ? expf(wv - mx) : 0.0f;
        float denom = e;
        #pragma unroll
        for (int o = 16; o > 0; o >>= 1)
            denom += __shfl_xor_sync(0xFFFFFFFFu, denom, o);
        float num = __shfl_sync(0xFFFFFFFFu, e, wi);
        scale = num / denom;
    } else {
        float mx = -INFINITY;
        for (int j = 0; j < n_winds; j++) mx = fmaxf(mx, wind_weights[j]);
        float denom = 0.0f, num = 0.0f;
        for (int j = 0; j < n_winds; j++) {
            float e = expf(wind_weights[j] - mx);
            denom += e;
            if (j == wi) num = e;
        }
        scale = num / denom;
    }

    if (lane == 0)
        out[warp] = (s / (float)hw) * scale;
}

extern "C" void kernel_launch(void* const* d_in, const int* in_sizes, int n_in,
                              void* d_out, int out_size)
{
    const float* x   = (const float*)d_in[0];
    const int*   idx = (const int*)d_in[1];
    const float* w   = (const float*)d_in[2];
    float*       out = (float*)d_out;

    int n_rows  = out_size;               // B*C
    int B       = in_sizes[1];
    int C       = n_rows / B;
    int hw      = in_sizes[0] / n_rows;   // H*W
    int n_winds = in_sizes[2];

    int warps_per_block = 16;             // 512 threads (best measured config)
    int blocks = (n_rows + warps_per_block - 1) / warps_per_block;
    wind_pool_kernel<<<blocks, warps_per_block * 32>>>(x, idx, w, out, n_rows, C, hw, n_winds);
}

// round 11
// speedup vs baseline: 1.0050x; 1.0050x over previous
#include <cuda_runtime.h>
#include <math.h>

// WindAdaptivePooling: out[b,c] = mean(x[b,c,:,:]) * softmax(wind_weights)[wind_indices[b]]
// x: [64, 1280, 32, 32] fp32 = 335.5 MB single-pass stream -> HBM-bound.
// FINAL KERNEL (R8 config, twice-confirmed). Evidence across 10 rounds:
//   R1/R5 52.7us baseline (one-shot grid, 8x float4 MLP=8/warp, DRAM 84.9%).
//   R2 __ldcs: neutral (B300 LTS cap is path-independent: LDG == LDG.cs == TMA).
//   R3 persistent, free regs: regs 44 -> occ 5/SM -> DRAM 80.3%. REGRESSED.
//   R4 persistent + reg cap: MLP serialized by 32-reg limit -> 77.5%. REGRESSED.
//   R6 softmax in load shadow: 52.2us, regs 57 (occ 39 -- DRAM invariant to occ).
//   R7 lane-parallel softmax AFTER reduce: 51.9us, regs 32, DRAM 85.3%. WIN.
//   R8 512-thr blocks: 51.7us, DRAM 85.4% (6.76 TB/s). WIN (small).
//   R9 1024-thr blocks: neutral. R10 rerun of R8: 51.94us -> noise band ±0.25us.
// Conclusion: 85% DRAM / ~6.75 TB/s is the sm_103a pure-read roofline for this
// pattern; bytes are irreducible; all identified mechanisms tested. Final.

__global__ void __launch_bounds__(512) wind_pool_kernel(
    const float* __restrict__ x,
    const int*   __restrict__ wind_indices,
    const float* __restrict__ wind_weights,
    float*       __restrict__ out,
    int n_rows,   // B*C
    int C,
    int hw,       // H*W elements per row
    int n_winds)
{
    int warp = (blockIdx.x * (int)blockDim.x + (int)threadIdx.x) >> 5;
    int lane = threadIdx.x & 31;
    if (warp >= n_rows) return;

    const float4* row4 = reinterpret_cast<const float4*>(x + (size_t)warp * hw);
    int n4 = hw >> 2;

    float s = 0.0f;
    if (n4 == 256) {
        // Fast path: HW=1024. 8 fully-unrolled independent float4 loads (MLP=8).
        float4 v0 = row4[lane + 0 * 32];
        float4 v1 = row4[lane + 1 * 32];
        float4 v2 = row4[lane + 2 * 32];
        float4 v3 = row4[lane + 3 * 32];
        float4 v4 = row4[lane + 4 * 32];
        float4 v5 = row4[lane + 5 * 32];
        float4 v6 = row4[lane + 6 * 32];
        float4 v7 = row4[lane + 7 * 32];
        s = (v0.x + v0.y + v0.z + v0.w) + (v1.x + v1.y + v1.z + v1.w)
          + (v2.x + v2.y + v2.z + v2.w) + (v3.x + v3.y + v3.z + v3.w)
          + (v4.x + v4.y + v4.z + v4.w) + (v5.x + v5.y + v5.z + v5.w)
          + (v6.x + v6.y + v6.z + v6.w) + (v7.x + v7.y + v7.z + v7.w);
    } else {
        for (int i = lane; i < n4; i += 32) {
            float4 v = row4[i];
            s += v.x + v.y + v.z + v.w;
        }
    }

    // Warp butterfly reduce of the row sum.
    #pragma unroll
    for (int o = 16; o > 0; o >>= 1)
        s += __shfl_xor_sync(0xFFFFFFFFu, s, o);

    // Lane-parallel softmax gather (temps live only AFTER loads retire -> 32 regs).
    int b  = warp / C;
    int wi = wind_indices[b];   // broadcast, L1/L2-hot
    float scale;
    if (n_winds <= 32) {
        float wv = (lane < n_winds) ? wind_weights[lane] : -INFINITY;
        float mx = wv;
        #pragma unroll
        for (int o = 16; o > 0; o >>= 1)
            mx = fmaxf(mx, __shfl_xor_sync(0xFFFFFFFFu, mx, o));
        float e = (lane < n_winds) ? expf(wv - mx) : 0.0f;
        float denom = e;
        #pragma unroll
        for (int o = 16; o > 0; o >>= 1)
            denom += __shfl_xor_sync(0xFFFFFFFFu, denom, o);
        float num = __shfl_sync(0xFFFFFFFFu, e, wi);
        scale = num / denom;
    } else {
        float mx = -INFINITY;
        for (int j = 0; j < n_winds; j++) mx = fmaxf(mx, wind_weights[j]);
        float denom = 0.0f, num = 0.0f;
        for (int j = 0; j < n_winds; j++) {
            float e = expf(wind_weights[j] - mx);
            denom += e;
            if (j == wi) num = e;
        }
        scale = num / denom;
    }

    if (lane == 0)
        out[warp] = (s / (float)hw) * scale;
}

extern "C" void kernel_launch(void* const* d_in, const int* in_sizes, int n_in,
                              void* d_out, int out_size)
{
    const float* x   = (const float*)d_in[0];
    const int*   idx = (const int*)d_in[1];
    const float* w   = (const float*)d_in[2];
    float*       out = (float*)d_out;

    int n_rows  = out_size;               // B*C
    int B       = in_sizes[1];
    int C       = n_rows / B;
    int hw      = in_sizes[0] / n_rows;   // H*W
    int n_winds = in_sizes[2];

    int warps_per_block = 16;             // 512 threads (best measured config)
    int blocks = (n_rows + warps_per_block - 1) / warps_per_block;
    wind_pool_kernel<<<blocks, warps_per_block * 32>>>(x, idx, w, out, n_rows, C, hw, n_winds);
}